// round 11
// baseline (speedup 1.0000x reference)
#include <cuda_runtime.h>
#include <cuda_fp16.h>
#include <cstdint>

#define D 128
#define VCAP 100000
#define CAP 128
#define TM_ROWS 96         // rows per tensor tile (M)
#define TC_THR 384         // 12 warps: 3 row groups (32 rows) x 4 col groups (32 cols)
#define KS2 264            // fp16 row stride for K=256 (+8 pad, stride/16 odd -> conflict-free)

// ---------------- scratch ----------------
__device__ float g_y  [(size_t)VCAP * D];   // layer activations (pre-BN), in-place across layers
__device__ float g_za [(size_t)VCAP * D];   // aggregated-input buffer
__device__ int   g_adj[(size_t)VCAP * CAP];
__device__ int   g_cnt[VCAP];
__device__ float g_dinv[VCAP];
__device__ float g_cntf[VCAP];
__device__ float g_stats[3 * 2 * D];        // per layer: colsum, colsumsq of y

// ---------------- helpers ----------------
__device__ __forceinline__ uint32_t smem_u32(const void* p) {
    return (uint32_t)__cvta_generic_to_shared(p);
}
__device__ __forceinline__ uint32_t pack_h2(float a, float b) {
    uint32_t r;
    asm("cvt.rn.f16x2.f32 %0, %1, %2;" : "=r"(r) : "f"(b), "f"(a));
    return r;
}
__device__ __forceinline__ void ldsm_x4(uint32_t addr, uint32_t r[4]) {
    asm volatile("ldmatrix.sync.aligned.m8n8.x4.shared.b16 {%0,%1,%2,%3}, [%4];"
                 : "=r"(r[0]), "=r"(r[1]), "=r"(r[2]), "=r"(r[3]) : "r"(addr));
}
__device__ __forceinline__ void mma_f16(float c[4], const uint32_t a[4],
                                        uint32_t b0, uint32_t b1) {
    asm volatile(
        "mma.sync.aligned.m16n8k16.row.col.f32.f16.f16.f32 "
        "{%0,%1,%2,%3}, {%4,%5,%6,%7}, {%8,%9}, {%0,%1,%2,%3};"
        : "+f"(c[0]), "+f"(c[1]), "+f"(c[2]), "+f"(c[3])
        : "r"(a[0]), "r"(a[1]), "r"(a[2]), "r"(a[3]), "r"(b0), "r"(b1));
}

// ---------------- prologue kernels ----------------
__global__ void zero_kernel(int V) {
    int i = blockIdx.x * blockDim.x + threadIdx.x;
    if (i < V) g_cnt[i] = 0;
    if (i < 3 * 2 * D) g_stats[i] = 0.0f;
}

__global__ void build_adj(const int* __restrict__ edges, int E) {
    int e = blockIdx.x * blockDim.x + threadIdx.x;
    if (e >= E) return;
    int a = edges[2 * e];
    int b = edges[2 * e + 1];
    int pa = atomicAdd(&g_cnt[a], 1);
    if (pa < CAP) g_adj[(size_t)a * CAP + pa] = b;
    int pb = atomicAdd(&g_cnt[b], 1);
    if (pb < CAP) g_adj[(size_t)b * CAP + pb] = a;
}

__global__ void dinv_kernel(int V) {
    int i = blockIdx.x * blockDim.x + threadIdx.x;
    if (i < V) {
        float c = (float)g_cnt[i];
        g_dinv[i] = 1.0f / (1.0f + c);
        g_cntf[i] = c;
    }
}

// ---------------- aggregation of inputs: za[v] = sum_{u in N(v)} f(src[u]) ----------------
__global__ void __launch_bounds__(256) agg_kernel(
    const float* __restrict__ src, int doNorm,
    const float* __restrict__ stats,
    const float* __restrict__ gamma, const float* __restrict__ beta,
    int V, float invV)
{
    __shared__ float s_sc[D], s_sh[D];

    int tid  = threadIdx.x;
    int wid  = tid >> 5;
    int lane = tid & 31;
    int c0   = lane * 4;

    if (tid < D) {
        if (doNorm) {
            float mu  = stats[tid] * invV;
            float var = stats[D + tid] * invV - mu * mu;
            float rs  = rsqrtf(var + 1e-5f);
            float sc  = gamma[tid] * rs;
            s_sc[tid] = sc;
            s_sh[tid] = beta[tid] - mu * sc;
        } else {
            s_sc[tid] = 1.0f;
            s_sh[tid] = 0.0f;
        }
    }
    __syncthreads();

    float4 scv = *(const float4*)(s_sc + c0);
    float4 shv = *(const float4*)(s_sh + c0);

    int warpStride = gridDim.x * 8;
    for (int v = blockIdx.x * 8 + wid; v < V; v += warpStride) {
        float4 acc = make_float4(0.f, 0.f, 0.f, 0.f);
        int n = g_cnt[v];
        const int* ap = g_adj + (size_t)v * CAP;
        int e = 0;
        if (doNorm) {
            for (; e + 3 < n; e += 4) {
                int u0 = ap[e], u1 = ap[e + 1], u2 = ap[e + 2], u3 = ap[e + 3];
                float4 t0 = __ldg((const float4*)(src + (size_t)u0 * D + c0));
                float4 t1 = __ldg((const float4*)(src + (size_t)u1 * D + c0));
                float4 t2 = __ldg((const float4*)(src + (size_t)u2 * D + c0));
                float4 t3 = __ldg((const float4*)(src + (size_t)u3 * D + c0));
                acc.x += fmaxf(fmaf(t0.x, scv.x, shv.x), 0.f) + fmaxf(fmaf(t1.x, scv.x, shv.x), 0.f)
                       + fmaxf(fmaf(t2.x, scv.x, shv.x), 0.f) + fmaxf(fmaf(t3.x, scv.x, shv.x), 0.f);
                acc.y += fmaxf(fmaf(t0.y, scv.y, shv.y), 0.f) + fmaxf(fmaf(t1.y, scv.y, shv.y), 0.f)
                       + fmaxf(fmaf(t2.y, scv.y, shv.y), 0.f) + fmaxf(fmaf(t3.y, scv.y, shv.y), 0.f);
                acc.z += fmaxf(fmaf(t0.z, scv.z, shv.z), 0.f) + fmaxf(fmaf(t1.z, scv.z, shv.z), 0.f)
                       + fmaxf(fmaf(t2.z, scv.z, shv.z), 0.f) + fmaxf(fmaf(t3.z, scv.z, shv.z), 0.f);
                acc.w += fmaxf(fmaf(t0.w, scv.w, shv.w), 0.f) + fmaxf(fmaf(t1.w, scv.w, shv.w), 0.f)
                       + fmaxf(fmaf(t2.w, scv.w, shv.w), 0.f) + fmaxf(fmaf(t3.w, scv.w, shv.w), 0.f);
            }
            for (; e < n; e++) {
                int u = ap[e];
                float4 t = __ldg((const float4*)(src + (size_t)u * D + c0));
                acc.x += fmaxf(fmaf(t.x, scv.x, shv.x), 0.f);
                acc.y += fmaxf(fmaf(t.y, scv.y, shv.y), 0.f);
                acc.z += fmaxf(fmaf(t.z, scv.z, shv.z), 0.f);
                acc.w += fmaxf(fmaf(t.w, scv.w, shv.w), 0.f);
            }
        } else {
            for (; e + 3 < n; e += 4) {
                int u0 = ap[e], u1 = ap[e + 1], u2 = ap[e + 2], u3 = ap[e + 3];
                float4 t0 = __ldg((const float4*)(src + (size_t)u0 * D + c0));
                float4 t1 = __ldg((const float4*)(src + (size_t)u1 * D + c0));
                float4 t2 = __ldg((const float4*)(src + (size_t)u2 * D + c0));
                float4 t3 = __ldg((const float4*)(src + (size_t)u3 * D + c0));
                acc.x += (t0.x + t1.x) + (t2.x + t3.x);
                acc.y += (t0.y + t1.y) + (t2.y + t3.y);
                acc.z += (t0.z + t1.z) + (t2.z + t3.z);
                acc.w += (t0.w + t1.w) + (t2.w + t3.w);
            }
            for (; e < n; e++) {
                int u = ap[e];
                float4 t = __ldg((const float4*)(src + (size_t)u * D + c0));
                acc.x += t.x; acc.y += t.y; acc.z += t.z; acc.w += t.w;
            }
        }
        *(float4*)(g_za + (size_t)v * D + c0) = acc;
    }
}

// ---------------- fused HMMA GEMM: y = dinv*( [f(z)|za] @ [W0|W1]^T + b0 + cnt*b1 ) ------------
// K = 256, N = 128. fp16 2-term (W split hi+lo). BN stats of y accumulated in epilogue.
__global__ void __launch_bounds__(TC_THR, 1)
gemm_fused(const float* __restrict__ zext, int layer,
           const float* __restrict__ W0, const float* __restrict__ b0,
           const float* __restrict__ W1, const float* __restrict__ b1,
           const float* __restrict__ gammaPrev, const float* __restrict__ betaPrev,
           float* __restrict__ statsOut, int V, float invV)
{
    extern __shared__ __align__(16) char smb[];
    __half* Bhi = (__half*)smb;                        // [128][KS2]
    __half* Blo = Bhi + 128 * KS2;                     // [128][KS2]
    __half* Ah  = Blo + 128 * KS2;                     // [96][KS2]

    __shared__ float s_sc[D], s_sh[D], s_b0[D], s_b1[D];
    __shared__ float s_sum[D], s_sq[D];

    const float* z = (layer == 0) ? zext : g_y;
    const bool doNorm = (layer != 0);

    int tid  = threadIdx.x;
    int wid  = tid >> 5;
    int lane = tid & 31;

    if (tid < D) {
        if (doNorm) {
            const float* st = g_stats + (layer - 1) * 2 * D;
            float mu  = st[tid] * invV;
            float var = st[D + tid] * invV - mu * mu;
            float rs  = rsqrtf(var + 1e-5f);
            float sc  = gammaPrev[tid] * rs;
            s_sc[tid] = sc;
            s_sh[tid] = betaPrev[tid] - mu * sc;
        }
        s_b0[tid] = b0[tid];
        s_b1[tid] = b1[tid];
        s_sum[tid] = 0.f;
        s_sq[tid]  = 0.f;
    }

    // --- convert [W0|W1] -> Bhi/Blo (fp16 hi + residual lo, once per block) ---
    for (int idx = tid; idx < 128 * 64; idx += TC_THR) {
        int n  = idx >> 6;
        int k4 = (idx & 63) * 4;
        const float* Wp = (k4 < D) ? (W0 + (size_t)n * D + k4)
                                   : (W1 + (size_t)n * D + (k4 - D));
        float4 w = *(const float4*)Wp;
        float h0 = __half2float(__float2half_rn(w.x));
        float h1 = __half2float(__float2half_rn(w.y));
        float h2 = __half2float(__float2half_rn(w.z));
        float h3 = __half2float(__float2half_rn(w.w));
        *(uint2*)(Bhi + n * KS2 + k4) = make_uint2(pack_h2(h0, h1), pack_h2(h2, h3));
        *(uint2*)(Blo + n * KS2 + k4) = make_uint2(pack_h2(w.x - h0, w.y - h1),
                                                   pack_h2(w.z - h2, w.w - h3));
    }

    // warp tiling: mw = row group (32 rows, 0..2), nw = col group (32 cols, 0..3)
    int mw = wid >> 2;
    int nw = wid & 3;
    int mrow0 = mw * 32;
    int ncolbase = nw * 32;

    uint32_t aOffB = (uint32_t)(((mrow0 + (lane & 15)) * KS2 + (lane >> 4) * 8) * 2);
    uint32_t aAddr0 = smem_u32(Ah) + aOffB;
    uint32_t aAddr1 = aAddr0 + 16 * KS2 * 2;

    uint32_t bOffB = (uint32_t)(((ncolbase + (lane & 15)) * KS2 + (lane >> 4) * 8) * 2);
    uint32_t bHiAddr = smem_u32(Bhi) + bOffB;
    uint32_t bLoAddr = smem_u32(Blo) + bOffB;

    int ncol = (lane & 3) * 2;

    // per-thread column stats accumulators (8 columns: 4 n-groups x 2)
    float psum[8], psq[8];
    #pragma unroll
    for (int i = 0; i < 8; i++) { psum[i] = 0.f; psq[i] = 0.f; }

    int numTiles = (V + TM_ROWS - 1) / TM_ROWS;
    __syncthreads();   // B + params ready

    for (int t = blockIdx.x; t < numTiles; t += gridDim.x) {
        int r0 = t * TM_ROWS;

        // --- convert A tile: cols 0..127 = f(z), cols 128..255 = za ---
        #pragma unroll
        for (int it = 0; it < 16; it++) {
            int f   = tid + it * TC_THR;
            int r   = f >> 6;
            int c4  = (f & 63) * 4;
            int row = r0 + r;
            float4 a;
            if (row < V) {
                if (c4 < D) {
                    a = *(const float4*)(z + (size_t)row * D + c4);
                    if (doNorm) {
                        a.x = fmaxf(fmaf(a.x, s_sc[c4 + 0], s_sh[c4 + 0]), 0.f);
                        a.y = fmaxf(fmaf(a.y, s_sc[c4 + 1], s_sh[c4 + 1]), 0.f);
                        a.z = fmaxf(fmaf(a.z, s_sc[c4 + 2], s_sh[c4 + 2]), 0.f);
                        a.w = fmaxf(fmaf(a.w, s_sc[c4 + 3], s_sh[c4 + 3]), 0.f);
                    }
                } else {
                    a = *(const float4*)(g_za + (size_t)row * D + (c4 - D));
                }
            } else {
                a = make_float4(0.f, 0.f, 0.f, 0.f);
            }
            *(uint2*)(Ah + r * KS2 + c4) = make_uint2(pack_h2(a.x, a.y), pack_h2(a.z, a.w));
        }
        __syncthreads();

        // --- accumulators (zero; bias added in epilogue) ---
        float acc[4][8];
        #pragma unroll
        for (int n = 0; n < 4; n++)
            #pragma unroll
            for (int j = 0; j < 8; j++) acc[n][j] = 0.f;

        // --- main MMA loop: 16 k-chunks, 2 terms ---
        #pragma unroll
        for (int kc = 0; kc < 16; kc++) {
            uint32_t a0[4], a1[4];
            ldsm_x4(aAddr0 + kc * 32, a0);
            ldsm_x4(aAddr1 + kc * 32, a1);
            #pragma unroll
            for (int np = 0; np < 2; np++) {
                uint32_t bhi[4], blo[4];
                uint32_t boff = (uint32_t)(np * 16 * KS2 * 2 + kc * 32);
                ldsm_x4(bHiAddr + boff, bhi);
                ldsm_x4(bLoAddr + boff, blo);
                float* aE = acc[np * 2];
                float* aO = acc[np * 2 + 1];
                mma_f16(aE,     a0, bhi[0], bhi[2]);
                mma_f16(aE,     a0, blo[0], blo[2]);
                mma_f16(aO,     a0, bhi[1], bhi[3]);
                mma_f16(aO,     a0, blo[1], blo[3]);
                mma_f16(aE + 4, a1, bhi[0], bhi[2]);
                mma_f16(aE + 4, a1, blo[0], blo[2]);
                mma_f16(aO + 4, a1, bhi[1], bhi[3]);
                mma_f16(aO + 4, a1, blo[1], blo[3]);
            }
        }

        // --- epilogue: y = dinv*(acc + b0 + cnt*b1), store + stats ---
        int rbase = r0 + mrow0 + (lane >> 2);
        #pragma unroll
        for (int rs = 0; rs < 4; rs++) {
            int row = rbase + rs * 8;
            if (row < V) {
                float dv = g_dinv[row];
                float cf = g_cntf[row];
                #pragma unroll
                for (int n = 0; n < 4; n++) {
                    int c = ncolbase + n * 8 + ncol;
                    int j = (rs >> 1) * 4 + (rs & 1) * 2;   // reg index: rs0->0, rs1->2, rs2->4, rs3->6
                    float y0 = dv * (acc[n][j]     + s_b0[c]     + cf * s_b1[c]);
                    float y1 = dv * (acc[n][j + 1] + s_b0[c + 1] + cf * s_b1[c + 1]);
                    *(float2*)(g_y + (size_t)row * D + c) = make_float2(y0, y1);
                    psum[n * 2 + 0] += y0; psq[n * 2 + 0] += y0 * y0;
                    psum[n * 2 + 1] += y1; psq[n * 2 + 1] += y1 * y1;
                }
            }
        }
        __syncthreads();   // MMA readers done before next conversion overwrites A
    }

    // --- fold per-thread stats into block smem, then global ---
    #pragma unroll
    for (int n = 0; n < 4; n++) {
        int c = ncolbase + n * 8 + ncol;
        atomicAdd(&s_sum[c],     psum[n * 2 + 0]);
        atomicAdd(&s_sum[c + 1], psum[n * 2 + 1]);
        atomicAdd(&s_sq[c],      psq[n * 2 + 0]);
        atomicAdd(&s_sq[c + 1],  psq[n * 2 + 1]);
    }
    __syncthreads();
    if (tid < D) {
        atomicAdd(&statsOut[tid],     s_sum[tid]);
        atomicAdd(&statsOut[D + tid], s_sq[tid]);
    }
}

// ---------------- final BN + ReLU + residual -> out ----------------
__global__ void __launch_bounds__(256) norm_final(
    const float* __restrict__ stats,
    const float* __restrict__ gamma, const float* __restrict__ beta,
    const float* __restrict__ res,
    float* __restrict__ out, int V, float invV)
{
    __shared__ float s_scale[D];
    __shared__ float s_shift[D];

    int tid = threadIdx.x;
    if (tid < D) {
        float mu  = stats[tid] * invV;
        float var = stats[D + tid] * invV - mu * mu;
        float rs  = rsqrtf(var + 1e-5f);
        float sc  = gamma[tid] * rs;
        s_scale[tid] = sc;
        s_shift[tid] = beta[tid] - mu * sc;
    }
    __syncthreads();

    int total = V * (D / 4);
    for (int f = blockIdx.x * blockDim.x + tid; f < total; f += gridDim.x * blockDim.x) {
        int c = (f & 31) * 4;
        float4 t = *(const float4*)(g_y + (size_t)f * 4);
        float4 r = *(const float4*)(res + (size_t)f * 4);
        float4 o;
        o.x = fmaxf(fmaf(t.x, s_scale[c + 0], s_shift[c + 0]) + r.x, 0.f);
        o.y = fmaxf(fmaf(t.y, s_scale[c + 1], s_shift[c + 1]) + r.y, 0.f);
        o.z = fmaxf(fmaf(t.z, s_scale[c + 2], s_shift[c + 2]) + r.z, 0.f);
        o.w = fmaxf(fmaf(t.w, s_scale[c + 3], s_shift[c + 3]) + r.w, 0.f);
        *(float4*)(out + (size_t)f * 4) = o;
    }
}

// ---------------- launch ----------------
extern "C" void kernel_launch(void* const* d_in, const int* in_sizes, int n_in,
                              void* d_out, int out_size)
{
    const float* features = (const float*)d_in[0];
    const int*   edges    = (const int*)  d_in[1];
    const float* W0       = (const float*)d_in[2];
    const float* b0       = (const float*)d_in[3];
    const float* W1       = (const float*)d_in[4];
    const float* b1       = (const float*)d_in[5];
    const float* gamma    = (const float*)d_in[6];
    const float* beta     = (const float*)d_in[7];
    float* out = (float*)d_out;

    int V = in_sizes[0] / D;
    int E = in_sizes[1] / 2;
    float invV = 1.0f / (float)V;

    // Bhi/Blo [128][KS2] + Ah [96][KS2], fp16
    const int SMEM_BYTES = (2 * 128 + TM_ROWS) * KS2 * 2;   // 185856
    cudaFuncSetAttribute(gemm_fused, cudaFuncAttributeMaxDynamicSharedMemorySize, SMEM_BYTES);

    float* statsP = nullptr;
    cudaGetSymbolAddress((void**)&statsP, g_stats);

    zero_kernel<<<(V + 255) / 256, 256>>>(V);
    build_adj<<<(E + 255) / 256, 256>>>(edges, E);
    dinv_kernel<<<(V + 255) / 256, 256>>>(V);

    for (int l = 0; l < 3; l++) {
        const float* src   = (l == 0) ? features : nullptr;  // g_y used inside for l>0
        const float* gPrev = (l == 0) ? gamma : gamma + (size_t)(l - 1) * D;
        const float* bPrev = (l == 0) ? beta  : beta  + (size_t)(l - 1) * D;
        const float* stPrev = statsP + (l == 0 ? 0 : (l - 1) * 2 * D);

        // aggregate inputs: za = sum_{u in N(v)} f(z[u])
        {
            float* ysrc = nullptr;
            cudaGetSymbolAddress((void**)&ysrc, g_y);
            agg_kernel<<<1184, 256>>>((l == 0) ? features : ysrc, (l == 0) ? 0 : 1,
                                      stPrev, gPrev, bPrev, V, invV);
        }

        gemm_fused<<<148, TC_THR, SMEM_BYTES>>>(
            features, l,
            W0 + (size_t)l * D * D, b0 + (size_t)l * D,
            W1 + (size_t)l * D * D, b1 + (size_t)l * D,
            gPrev, bPrev,
            statsP + l * 2 * D, V, invV);
    }

    norm_final<<<1184, 256>>>(statsP + 2 * 2 * D,
                              gamma + 2 * (size_t)D, beta + 2 * (size_t)D,
                              features, out, V, invV);
}

// round 12
// speedup vs baseline: 1.5609x; 1.5609x over previous
#include <cuda_runtime.h>
#include <cuda_fp16.h>
#include <cstdint>

#define D 128
#define VCAP 100000
#define CAP 128
#define TM_ROWS 96         // rows per tensor tile (M)
#define TC_THR 384         // 12 warps: 3 row groups (32 rows) x 4 col groups (64 cols)
#define KS 136             // fp16 row stride (128 + 8 pad) -> conflict-free LDSM

// ---------------- scratch ----------------
__device__ float  g_h0[(size_t)VCAP * D];
__device__ __half g_h1[(size_t)VCAP * D];   // h1 stored fp16 (halves gather traffic)
__device__ float  g_y [(size_t)VCAP * D];
__device__ int    g_adj[(size_t)VCAP * CAP];
__device__ int    g_cnt[VCAP];
__device__ float  g_dinv[VCAP];
__device__ float  g_stats[3 * 2 * D];

// ---------------- helpers ----------------
__device__ __forceinline__ uint32_t smem_u32(const void* p) {
    return (uint32_t)__cvta_generic_to_shared(p);
}
// pack two f32 -> f16x2 (a -> lo, b -> hi)
__device__ __forceinline__ uint32_t pack_h2(float a, float b) {
    uint32_t r;
    asm("cvt.rn.f16x2.f32 %0, %1, %2;" : "=r"(r) : "f"(b), "f"(a));
    return r;
}
__device__ __forceinline__ void ldsm_x4(uint32_t addr, uint32_t r[4]) {
    asm volatile("ldmatrix.sync.aligned.m8n8.x4.shared.b16 {%0,%1,%2,%3}, [%4];"
                 : "=r"(r[0]), "=r"(r[1]), "=r"(r[2]), "=r"(r[3]) : "r"(addr));
}
__device__ __forceinline__ void mma_f16(float c[4], const uint32_t a[4],
                                        uint32_t b0, uint32_t b1) {
    asm volatile(
        "mma.sync.aligned.m16n8k16.row.col.f32.f16.f16.f32 "
        "{%0,%1,%2,%3}, {%4,%5,%6,%7}, {%8,%9}, {%0,%1,%2,%3};"
        : "+f"(c[0]), "+f"(c[1]), "+f"(c[2]), "+f"(c[3])
        : "r"(a[0]), "r"(a[1]), "r"(a[2]), "r"(a[3]), "r"(b0), "r"(b1));
}

// ---------------- prologue kernels ----------------
__global__ void zero_kernel(int V) {
    int i = blockIdx.x * blockDim.x + threadIdx.x;
    if (i < V) g_cnt[i] = 0;
    if (i < 3 * 2 * D) g_stats[i] = 0.0f;
}

__global__ void build_adj(const int* __restrict__ edges, int E) {
    int e = blockIdx.x * blockDim.x + threadIdx.x;
    if (e >= E) return;
    int a = edges[2 * e];
    int b = edges[2 * e + 1];
    int pa = atomicAdd(&g_cnt[a], 1);
    if (pa < CAP) g_adj[(size_t)a * CAP + pa] = b;
    int pb = atomicAdd(&g_cnt[b], 1);
    if (pb < CAP) g_adj[(size_t)b * CAP + pb] = a;
}

__global__ void dinv_kernel(int V) {
    int i = blockIdx.x * blockDim.x + threadIdx.x;
    if (i < V) g_dinv[i] = 1.0f / (1.0f + (float)g_cnt[i]);
}

// ---------------- HMMA dual GEMM (fp16, 2 terms: x_h*W_hi + x_h*W_lo) ----------------
// h0 = f(x) @ W0^T + b0 (fp32) ; h1 = f(x) @ W1^T + b1 (stored fp16)
__global__ void __launch_bounds__(TC_THR, 1)
gemm_dual_tc(const float* __restrict__ xext, int layer,
             const float* __restrict__ W0, const float* __restrict__ b0,
             const float* __restrict__ W1, const float* __restrict__ b1,
             const float* __restrict__ gammaPrev, const float* __restrict__ betaPrev,
             int V, float invV)
{
    extern __shared__ __align__(16) char smb[];
    __half* Bhi = (__half*)smb;                       // [256][KS]
    __half* Blo = Bhi + 256 * KS;                     // [256][KS]
    __half* Ah  = Blo + 256 * KS;                     // [96][KS]

    __shared__ float s_sc[D], s_sh[D], s_bias[256];

    const float* x = (layer == 0) ? xext : g_y;
    const bool doNorm = (layer != 0);

    int tid  = threadIdx.x;
    int wid  = tid >> 5;
    int lane = tid & 31;

    if (tid < D) {
        if (doNorm) {
            const float* st = g_stats + (layer - 1) * 2 * D;
            float mu  = st[tid] * invV;
            float var = st[D + tid] * invV - mu * mu;
            float rs  = rsqrtf(var + 1e-5f);
            float sc  = gammaPrev[tid] * rs;
            s_sc[tid] = sc;
            s_sh[tid] = betaPrev[tid] - mu * sc;
        }
        s_bias[tid]     = b0[tid];
        s_bias[tid + D] = b1[tid];
    }

    // --- convert W0||W1 -> Bhi/Blo (fp16 hi + residual lo, once per block) ---
    for (int idx = tid; idx < 256 * 32; idx += TC_THR) {
        int n  = idx >> 5;
        int k4 = (idx & 31) * 4;
        const float* Wp = (n < D) ? (W0 + (size_t)n * D + k4)
                                  : (W1 + (size_t)(n - D) * D + k4);
        float4 w = *(const float4*)Wp;
        float h0 = __half2float(__float2half_rn(w.x));
        float h1 = __half2float(__float2half_rn(w.y));
        float h2 = __half2float(__float2half_rn(w.z));
        float h3 = __half2float(__float2half_rn(w.w));
        *(uint2*)(Bhi + n * KS + k4) = make_uint2(pack_h2(h0, h1), pack_h2(h2, h3));
        *(uint2*)(Blo + n * KS + k4) = make_uint2(pack_h2(w.x - h0, w.y - h1),
                                                  pack_h2(w.z - h2, w.w - h3));
    }

    // warp tiling: mw = row group (32 rows, 0..2), nw = col group (64 cols, 0..3)
    int mw = wid >> 2;
    int nw = wid & 3;
    int mrow0 = mw * 32;
    int ncolbase = nw * 64;     // within 0..255

    // A ldmatrix addresses: two 16-row sets
    uint32_t aOffB = (uint32_t)(((mrow0 + (lane & 15)) * KS + (lane >> 4) * 8) * 2);
    uint32_t aAddr0 = smem_u32(Ah) + aOffB;
    uint32_t aAddr1 = aAddr0 + 16 * KS * 2;

    // B ldmatrix x4 addresses: 16 n-rows per load (2 n-groups of 8)
    uint32_t bOffB = (uint32_t)(((ncolbase + (lane & 15)) * KS + (lane >> 4) * 8) * 2);
    uint32_t bHiAddr = smem_u32(Bhi) + bOffB;
    uint32_t bLoAddr = smem_u32(Blo) + bOffB;

    int ncol = (lane & 3) * 2;

    int numTiles = (V + TM_ROWS - 1) / TM_ROWS;
    int tFirst = blockIdx.x;

    // --- register prefetch of first tile ---
    float4 pf[8];
    {
        int r0 = tFirst * TM_ROWS;
        #pragma unroll
        for (int it = 0; it < 8; it++) {
            int f   = tid + it * TC_THR;
            int row = r0 + (f >> 5);
            int k4  = (f & 31) * 4;
            pf[it] = (tFirst < numTiles && row < V)
                   ? *(const float4*)(x + (size_t)row * D + k4)
                   : make_float4(0.f, 0.f, 0.f, 0.f);
        }
    }

    for (int t = tFirst; t < numTiles; t += gridDim.x) {
        int r0 = t * TM_ROWS;

        // --- convert prefetched x tile -> Ah (fused BN+ReLU for layers 1,2) ---
        #pragma unroll
        for (int it = 0; it < 8; it++) {
            int f  = tid + it * TC_THR;
            int r  = f >> 5;
            int k4 = (f & 31) * 4;
            float4 a = pf[it];
            if (doNorm) {
                a.x = fmaxf(fmaf(a.x, s_sc[k4 + 0], s_sh[k4 + 0]), 0.f);
                a.y = fmaxf(fmaf(a.y, s_sc[k4 + 1], s_sh[k4 + 1]), 0.f);
                a.z = fmaxf(fmaf(a.z, s_sc[k4 + 2], s_sh[k4 + 2]), 0.f);
                a.w = fmaxf(fmaf(a.w, s_sc[k4 + 3], s_sh[k4 + 3]), 0.f);
                if (r0 + r >= V) a = make_float4(0.f, 0.f, 0.f, 0.f);
            }
            *(uint2*)(Ah + r * KS + k4) = make_uint2(pack_h2(a.x, a.y), pack_h2(a.z, a.w));
        }
        __syncthreads();

        // --- prefetch next tile (latency hidden under MMA loop) ---
        int tn = t + gridDim.x;
        if (tn < numTiles) {
            int rn0 = tn * TM_ROWS;
            #pragma unroll
            for (int it = 0; it < 8; it++) {
                int f   = tid + it * TC_THR;
                int row = rn0 + (f >> 5);
                int k4  = (f & 31) * 4;
                pf[it] = (row < V) ? *(const float4*)(x + (size_t)row * D + k4)
                                   : make_float4(0.f, 0.f, 0.f, 0.f);
            }
        }

        // --- accumulators init to bias: acc[n][0..3] rowset0, [4..7] rowset1 ---
        float acc[8][8];
        #pragma unroll
        for (int n = 0; n < 8; n++) {
            float bx = s_bias[ncolbase + n * 8 + ncol];
            float by = s_bias[ncolbase + n * 8 + ncol + 1];
            acc[n][0] = bx; acc[n][1] = by; acc[n][2] = bx; acc[n][3] = by;
            acc[n][4] = bx; acc[n][5] = by; acc[n][6] = bx; acc[n][7] = by;
        }

        // --- main MMA loop: 8 k-chunks, 2 terms ---
        #pragma unroll
        for (int kc = 0; kc < 8; kc++) {
            uint32_t a0[4], a1[4];
            ldsm_x4(aAddr0 + kc * 32, a0);
            ldsm_x4(aAddr1 + kc * 32, a1);
            #pragma unroll
            for (int np = 0; np < 4; np++) {
                uint32_t bhi[4], blo[4];
                uint32_t boff = (uint32_t)(np * 16 * KS * 2 + kc * 32);
                ldsm_x4(bHiAddr + boff, bhi);
                ldsm_x4(bLoAddr + boff, blo);
                float* aE = acc[np * 2];
                float* aO = acc[np * 2 + 1];
                mma_f16(aE,     a0, bhi[0], bhi[2]);
                mma_f16(aE,     a0, blo[0], blo[2]);
                mma_f16(aO,     a0, bhi[1], bhi[3]);
                mma_f16(aO,     a0, blo[1], blo[3]);
                mma_f16(aE + 4, a1, bhi[0], bhi[2]);
                mma_f16(aE + 4, a1, blo[0], blo[2]);
                mma_f16(aO + 4, a1, bhi[1], bhi[3]);
                mma_f16(aO + 4, a1, blo[1], blo[3]);
            }
        }

        // --- epilogue: h0 cols -> fp32 g_h0 ; h1 cols -> fp16 g_h1 ---
        int rA = r0 + mrow0 + (lane >> 2);
        int cb = (nw & 1) * 64;
        if (nw < 2) {
            #pragma unroll
            for (int n = 0; n < 8; n++) {
                int c = cb + n * 8 + ncol;
                if (rA < V)      *(float2*)(g_h0 + (size_t)rA * D + c)        = make_float2(acc[n][0], acc[n][1]);
                if (rA + 8 < V)  *(float2*)(g_h0 + (size_t)(rA + 8) * D + c)  = make_float2(acc[n][2], acc[n][3]);
                if (rA + 16 < V) *(float2*)(g_h0 + (size_t)(rA + 16) * D + c) = make_float2(acc[n][4], acc[n][5]);
                if (rA + 24 < V) *(float2*)(g_h0 + (size_t)(rA + 24) * D + c) = make_float2(acc[n][6], acc[n][7]);
            }
        } else {
            #pragma unroll
            for (int n = 0; n < 8; n++) {
                int c = cb + n * 8 + ncol;
                if (rA < V)      *(uint32_t*)(g_h1 + (size_t)rA * D + c)        = pack_h2(acc[n][0], acc[n][1]);
                if (rA + 8 < V)  *(uint32_t*)(g_h1 + (size_t)(rA + 8) * D + c)  = pack_h2(acc[n][2], acc[n][3]);
                if (rA + 16 < V) *(uint32_t*)(g_h1 + (size_t)(rA + 16) * D + c) = pack_h2(acc[n][4], acc[n][5]);
                if (rA + 24 < V) *(uint32_t*)(g_h1 + (size_t)(rA + 24) * D + c) = pack_h2(acc[n][6], acc[n][7]);
            }
        }
        __syncthreads();   // MMA readers done before next conversion overwrites A
    }
}

// ---------------- aggregation + BN stats (h1 gathered as fp16) ----------------
__global__ void __launch_bounds__(256) agg_kernel(float* __restrict__ stats, int V)
{
    __shared__ float s_sum[D];
    __shared__ float s_sq[D];

    int tid  = threadIdx.x;
    int wid  = tid >> 5;
    int lane = tid & 31;
    int c0   = lane * 4;

    if (tid < D) { s_sum[tid] = 0.f; s_sq[tid] = 0.f; }
    __syncthreads();

    float4 psum = make_float4(0.f, 0.f, 0.f, 0.f);
    float4 psq  = make_float4(0.f, 0.f, 0.f, 0.f);

    int warpStride = gridDim.x * 8;
    for (int v = blockIdx.x * 8 + wid; v < V; v += warpStride) {
        float4 acc = *(const float4*)(g_h0 + (size_t)v * D + c0);
        int n = g_cnt[v];
        const int* ap = g_adj + (size_t)v * CAP;
        int e = 0;
        for (; e + 3 < n; e += 4) {
            int u0 = ap[e], u1 = ap[e + 1], u2 = ap[e + 2], u3 = ap[e + 3];
            uint2 p0 = __ldg((const uint2*)(g_h1 + (size_t)u0 * D + c0));
            uint2 p1 = __ldg((const uint2*)(g_h1 + (size_t)u1 * D + c0));
            uint2 p2 = __ldg((const uint2*)(g_h1 + (size_t)u2 * D + c0));
            uint2 p3 = __ldg((const uint2*)(g_h1 + (size_t)u3 * D + c0));
            float2 a0 = __half22float2(*(const __half2*)&p0.x);
            float2 b0 = __half22float2(*(const __half2*)&p0.y);
            float2 a1 = __half22float2(*(const __half2*)&p1.x);
            float2 b1 = __half22float2(*(const __half2*)&p1.y);
            float2 a2 = __half22float2(*(const __half2*)&p2.x);
            float2 b2 = __half22float2(*(const __half2*)&p2.y);
            float2 a3 = __half22float2(*(const __half2*)&p3.x);
            float2 b3 = __half22float2(*(const __half2*)&p3.y);
            acc.x += (a0.x + a1.x) + (a2.x + a3.x);
            acc.y += (a0.y + a1.y) + (a2.y + a3.y);
            acc.z += (b0.x + b1.x) + (b2.x + b3.x);
            acc.w += (b0.y + b1.y) + (b2.y + b3.y);
        }
        for (; e < n; e++) {
            int u = ap[e];
            uint2 p = __ldg((const uint2*)(g_h1 + (size_t)u * D + c0));
            float2 a = __half22float2(*(const __half2*)&p.x);
            float2 b = __half22float2(*(const __half2*)&p.y);
            acc.x += a.x; acc.y += a.y; acc.z += b.x; acc.w += b.y;
        }
        float dv = g_dinv[v];
        acc.x *= dv; acc.y *= dv; acc.z *= dv; acc.w *= dv;
        *(float4*)(g_y + (size_t)v * D + c0) = acc;

        psum.x += acc.x; psum.y += acc.y; psum.z += acc.z; psum.w += acc.w;
        psq.x  += acc.x * acc.x; psq.y += acc.y * acc.y;
        psq.z  += acc.z * acc.z; psq.w += acc.w * acc.w;
    }

    atomicAdd(&s_sum[c0 + 0], psum.x);
    atomicAdd(&s_sum[c0 + 1], psum.y);
    atomicAdd(&s_sum[c0 + 2], psum.z);
    atomicAdd(&s_sum[c0 + 3], psum.w);
    atomicAdd(&s_sq[c0 + 0],  psq.x);
    atomicAdd(&s_sq[c0 + 1],  psq.y);
    atomicAdd(&s_sq[c0 + 2],  psq.z);
    atomicAdd(&s_sq[c0 + 3],  psq.w);
    __syncthreads();

    if (tid < D) {
        atomicAdd(&stats[tid],     s_sum[tid]);
        atomicAdd(&stats[D + tid], s_sq[tid]);
    }
}

// ---------------- final BN + ReLU + residual -> out ----------------
__global__ void __launch_bounds__(256) norm_final(
    const float* __restrict__ stats,
    const float* __restrict__ gamma, const float* __restrict__ beta,
    const float* __restrict__ res,
    float* __restrict__ out, int V, float invV)
{
    __shared__ float s_scale[D];
    __shared__ float s_shift[D];

    int tid = threadIdx.x;
    if (tid < D) {
        float mu  = stats[tid] * invV;
        float var = stats[D + tid] * invV - mu * mu;
        float rs  = rsqrtf(var + 1e-5f);
        float sc  = gamma[tid] * rs;
        s_scale[tid] = sc;
        s_shift[tid] = beta[tid] - mu * sc;
    }
    __syncthreads();

    int total = V * (D / 4);
    for (int f = blockIdx.x * blockDim.x + tid; f < total; f += gridDim.x * blockDim.x) {
        int c = (f & 31) * 4;
        float4 t = *(const float4*)(g_y + (size_t)f * 4);
        float4 r = *(const float4*)(res + (size_t)f * 4);
        float4 o;
        o.x = fmaxf(fmaf(t.x, s_scale[c + 0], s_shift[c + 0]) + r.x, 0.f);
        o.y = fmaxf(fmaf(t.y, s_scale[c + 1], s_shift[c + 1]) + r.y, 0.f);
        o.z = fmaxf(fmaf(t.z, s_scale[c + 2], s_shift[c + 2]) + r.z, 0.f);
        o.w = fmaxf(fmaf(t.w, s_scale[c + 3], s_shift[c + 3]) + r.w, 0.f);
        *(float4*)(out + (size_t)f * 4) = o;
    }
}

// ---------------- launch ----------------
extern "C" void kernel_launch(void* const* d_in, const int* in_sizes, int n_in,
                              void* d_out, int out_size)
{
    const float* features = (const float*)d_in[0];
    const int*   edges    = (const int*)  d_in[1];
    const float* W0       = (const float*)d_in[2];
    const float* b0       = (const float*)d_in[3];
    const float* W1       = (const float*)d_in[4];
    const float* b1       = (const float*)d_in[5];
    const float* gamma    = (const float*)d_in[6];
    const float* beta     = (const float*)d_in[7];
    float* out = (float*)d_out;

    int V = in_sizes[0] / D;
    int E = in_sizes[1] / 2;
    float invV = 1.0f / (float)V;

    // Bhi/Blo [256][KS] + Ah [96][KS], fp16
    const int SMEM_BYTES = (2 * 256 + TM_ROWS) * KS * 2;
    cudaFuncSetAttribute(gemm_dual_tc, cudaFuncAttributeMaxDynamicSharedMemorySize, SMEM_BYTES);

    float* statsP = nullptr;
    cudaGetSymbolAddress((void**)&statsP, g_stats);

    zero_kernel<<<(V + 255) / 256, 256>>>(V);
    build_adj<<<(E + 255) / 256, 256>>>(edges, E);
    dinv_kernel<<<(V + 255) / 256, 256>>>(V);

    for (int l = 0; l < 3; l++) {
        const float* gPrev = (l == 0) ? nullptr : gamma + (size_t)(l - 1) * D;
        const float* bPrev = (l == 0) ? nullptr : beta  + (size_t)(l - 1) * D;
        gemm_dual_tc<<<148, TC_THR, SMEM_BYTES>>>(
            features, l,
            W0 + (size_t)l * D * D, b0 + (size_t)l * D,
            W1 + (size_t)l * D * D, b1 + (size_t)l * D,
            gPrev, bPrev, V, invV);

        agg_kernel<<<1184, 256>>>(statsP + l * 2 * D, V);
    }

    norm_final<<<1184, 256>>>(statsP + 2 * 2 * D,
                              gamma + 2 * (size_t)D, beta + 2 * (size_t)D,
                              features, out, V, invV);
}